// round 8
// baseline (speedup 1.0000x reference)
#include <cuda_runtime.h>
#include <cuda_bf16.h>
#include <math.h>
#include <stdint.h>

#define HID 128
#define NLV 262144

// ---------------- device buffers (static = allocation-guard safe) ----------------
__device__ __nv_bfloat16 g_Ahi[(size_t)131072 * 256];   // 64 MB
__device__ __nv_bfloat16 g_Alo[(size_t)131072 * 256];   // 64 MB
__device__ __nv_bfloat16 g_Bhi[(size_t)65536 * 256];    // 32 MB
__device__ __nv_bfloat16 g_Blo[(size_t)65536 * 256];    // 32 MB
// K-major split weights (same layout as originals: W[k][n]).
__device__ __nv_bfloat16 g_WLhi[256 * 128], g_WLlo[256 * 128];  // vstack(W_l,W_r)
__device__ __nv_bfloat16 g_WIhi[64 * 128],  g_WIlo[64 * 128];   // W_in
__device__ float g_bsum[128];                                   // b_l + b_r

// ---------------- helpers ----------------
__device__ __forceinline__ uint32_t f2bf2(float a, float b) {
    uint32_t r;
    asm("cvt.rn.bf16x2.f32 %0, %1, %2;" : "=r"(r) : "f"(b), "f"(a));
    return r;
}
__device__ __forceinline__ float bf_lo(uint32_t p) { return __uint_as_float(p << 16); }
__device__ __forceinline__ float bf_hi(uint32_t p) { return __uint_as_float(p & 0xFFFF0000u); }

__device__ __forceinline__ void ldm_x4(uint32_t* r, uint32_t addr) {
    asm volatile("ldmatrix.sync.aligned.m8n8.x4.shared.b16 {%0,%1,%2,%3}, [%4];"
                 : "=r"(r[0]), "=r"(r[1]), "=r"(r[2]), "=r"(r[3]) : "r"(addr));
}
__device__ __forceinline__ void ldm_x4_t(uint32_t* r, uint32_t addr) {
    asm volatile("ldmatrix.sync.aligned.m8n8.x4.trans.shared.b16 {%0,%1,%2,%3}, [%4];"
                 : "=r"(r[0]), "=r"(r[1]), "=r"(r[2]), "=r"(r[3]) : "r"(addr));
}
__device__ __forceinline__ void mma_bf16(float* c, const uint32_t* a, const uint32_t* b) {
    asm volatile("mma.sync.aligned.m16n8k16.row.col.f32.bf16.bf16.f32 "
                 "{%0,%1,%2,%3}, {%4,%5,%6,%7}, {%8,%9}, {%0,%1,%2,%3};"
                 : "+f"(c[0]), "+f"(c[1]), "+f"(c[2]), "+f"(c[3])
                 : "r"(a[0]), "r"(a[1]), "r"(a[2]), "r"(a[3]), "r"(b[0]), "r"(b[1]));
}
__device__ __forceinline__ void cp16(uint32_t dst, const void* src) {
    asm volatile("cp.async.ca.shared.global [%0], [%1], 16;" :: "r"(dst), "l"(src));
}
#define CP_COMMIT() asm volatile("cp.async.commit_group;" ::: "memory")
#define CP_WAIT(N)  asm volatile("cp.async.wait_group %0;" :: "n"(N) : "memory")

// A rows are 128B, W rows are 256B; permute 16B chunks for conflict-free ldmatrix.
#define SWZA(o) ((o) ^ ((((uint32_t)(o)) >> 3) & 0x70))
#define SWZW(o) ((o) ^ (((((uint32_t)(o)) >> 8) & 7) << 4))

// ---------------- smem layout: bias + 2 x 64KB stage buffers ----------------
#define SM_BIAS 0
#define SM_BUF  1024
#define BUF_SZ  65536
#define OFF_AHI 0
#define OFF_ALO 16384
#define OFF_WHI 32768
#define OFF_WLO 49152
#define SMEM_MAIN (1024 + 2 * BUF_SZ)
#define SMEM_LEAF (1024 + BUF_SZ)

// ---------------- prep ----------------
__global__ void prep_kernel(const float* __restrict__ W_in,
                            const float* __restrict__ W_l, const float* __restrict__ b_l,
                            const float* __restrict__ W_r, const float* __restrict__ b_r) {
    int t = blockIdx.x * blockDim.x + threadIdx.x;
    int stride = gridDim.x * blockDim.x;
    for (int idx = t; idx < 256 * 128; idx += stride) {
        float w = (idx < 128 * 128) ? W_l[idx] : W_r[idx - 128 * 128];
        __nv_bfloat16 h = __float2bfloat16(w);
        g_WLhi[idx] = h;
        g_WLlo[idx] = __float2bfloat16(w - __bfloat162float(h));
    }
    for (int idx = t; idx < 64 * 128; idx += stride) {
        float w = W_in[idx];
        __nv_bfloat16 h = __float2bfloat16(w);
        g_WIhi[idx] = h;
        g_WIlo[idx] = __float2bfloat16(w - __bfloat162float(h));
    }
    if (t < 128) g_bsum[t] = b_l[t] + b_r[t];
}

// ---------------- main level kernel ----------------
// H[Mo,128] = tanh(A[Mo,K] @ W[K,128] + bias), 3-pass bf16-split via mma.sync.
// 512 threads, 16 warps (8 m x 2 n), warp tile 16x64, CTA tile 128x128.
// Non-leaf: cp.async double-buffered K stages. Writes next-level paired-row pairs.
template <int K, bool LEAF>
__global__ void __launch_bounds__(512, 1)
rnn_level(const float* __restrict__ leafX,
          const __nv_bfloat16* __restrict__ Ahi, const __nv_bfloat16* __restrict__ Alo,
          const __nv_bfloat16* __restrict__ Whi, const __nv_bfloat16* __restrict__ Wlo,
          const float* __restrict__ bias,
          __nv_bfloat16* __restrict__ nHi, __nv_bfloat16* __restrict__ nLo) {
    extern __shared__ char smem[];
    const uint32_t sb = (uint32_t)__cvta_generic_to_shared(smem);
    const int tid = threadIdx.x, l = tid & 31, wid = tid >> 5;
    const int wm = wid & 7, wn = wid >> 3;          // warp grid 8 (m) x 2 (n)
    const int m0 = blockIdx.x * 128;
    constexpr int NST = K / 64;

    if (tid < 128) ((float*)(smem + SM_BIAS))[tid] = bias[tid];

    float acc[8][4];
    #pragma unroll
    for (int nt = 0; nt < 8; nt++)
        #pragma unroll
        for (int q = 0; q < 4; q++) acc[nt][q] = 0.f;

    // ---- stage loader (cp.async, non-leaf) ----
    auto load_stage = [&](int st, int buf) {
        const uint32_t bb = sb + SM_BUF + buf * BUF_SZ;
        #pragma unroll 2
        for (int i = tid; i < 1024; i += 512) {
            int r = i >> 3, kg = i & 7;
            uint32_t off = SWZA((uint32_t)(r * 128 + kg * 16));
            size_t gi = (size_t)(m0 + r) * K + st * 64 + kg * 8;
            cp16(bb + OFF_AHI + off, Ahi + gi);
            cp16(bb + OFF_ALO + off, Alo + gi);
        }
        #pragma unroll 2
        for (int i = tid; i < 1024; i += 512) {
            int kr = i >> 4, ch = i & 15;
            uint32_t off = SWZW((uint32_t)(kr * 256 + ch * 16));
            size_t gi = (size_t)(st * 64 + kr) * 128 + ch * 8;
            cp16(bb + OFF_WHI + off, Whi + gi);
            cp16(bb + OFF_WLO + off, Wlo + gi);
        }
    };

    // ---- compute one 64-wide K stage from a buffer ----
    auto compute_stage = [&](int buf) {
        const uint32_t bb = sb + SM_BUF + buf * BUF_SZ;
        #pragma unroll
        for (int ks = 0; ks < 4; ks++) {
            uint32_t ah[4], al[4], bh[8][2], bl[8][2];
            {
                int row = wm * 16 + (l & 15);
                uint32_t aoff = SWZA((uint32_t)(row * 128 + ks * 32 + (l >> 4) * 16));
                ldm_x4(ah, bb + OFF_AHI + aoff);
                ldm_x4(al, bb + OFF_ALO + aoff);
            }
            #pragma unroll
            for (int ntp = 0; ntp < 4; ntp++) {
                int krow = ks * 16 + (l & 15);
                int nb   = (wn * 64 + ntp * 16 + (l >> 4) * 8) * 2;
                uint32_t woff = SWZW((uint32_t)(krow * 256 + nb));
                uint32_t t4[4];
                ldm_x4_t(t4, bb + OFF_WHI + woff);
                bh[ntp * 2][0] = t4[0]; bh[ntp * 2][1] = t4[1];
                bh[ntp * 2 + 1][0] = t4[2]; bh[ntp * 2 + 1][1] = t4[3];
                ldm_x4_t(t4, bb + OFF_WLO + woff);
                bl[ntp * 2][0] = t4[0]; bl[ntp * 2][1] = t4[1];
                bl[ntp * 2 + 1][0] = t4[2]; bl[ntp * 2 + 1][1] = t4[3];
            }
            #pragma unroll
            for (int nt = 0; nt < 8; nt++) mma_bf16(acc[nt], ah, bh[nt]);
            #pragma unroll
            for (int nt = 0; nt < 8; nt++) mma_bf16(acc[nt], ah, bl[nt]);
            #pragma unroll
            for (int nt = 0; nt < 8; nt++) mma_bf16(acc[nt], al, bh[nt]);
        }
    };

    if (LEAF) {
        // Single stage: W via cp.async, A converted fp32->bf16 hi/lo in registers.
        const uint32_t bb = sb + SM_BUF;
        #pragma unroll 2
        for (int i = tid; i < 1024; i += 512) {
            int kr = i >> 4, ch = i & 15;
            uint32_t off = SWZW((uint32_t)(kr * 256 + ch * 16));
            size_t gi = (size_t)kr * 128 + ch * 8;
            cp16(bb + OFF_WHI + off, Whi + gi);
            cp16(bb + OFF_WLO + off, Wlo + gi);
        }
        CP_COMMIT();
        #pragma unroll 2
        for (int i = tid; i < 1024; i += 512) {
            int r = i >> 3, kg = i & 7;
            const float* src = leafX + (size_t)(m0 + r) * 64 + kg * 8;
            float4 f0 = *(const float4*)src;
            float4 f1 = *(const float4*)(src + 4);
            float xs[8] = {f0.x, f0.y, f0.z, f0.w, f1.x, f1.y, f1.z, f1.w};
            uint32_t hp[4], lp[4];
            #pragma unroll
            for (int j = 0; j < 4; j++) {
                hp[j] = f2bf2(xs[2 * j], xs[2 * j + 1]);
                lp[j] = f2bf2(xs[2 * j] - bf_lo(hp[j]), xs[2 * j + 1] - bf_hi(hp[j]));
            }
            uint32_t off = SWZA((uint32_t)(r * 128 + kg * 16));
            *(uint4*)(smem + SM_BUF + OFF_AHI + off) = make_uint4(hp[0], hp[1], hp[2], hp[3]);
            *(uint4*)(smem + SM_BUF + OFF_ALO + off) = make_uint4(lp[0], lp[1], lp[2], lp[3]);
        }
        CP_WAIT(0);
        __syncthreads();
        compute_stage(0);
    } else {
        load_stage(0, 0);
        CP_COMMIT();
        for (int st = 0; st < NST; st++) {
            if (st + 1 < NST) {
                load_stage(st + 1, (st + 1) & 1);
                CP_COMMIT();
                CP_WAIT(1);
            } else {
                CP_WAIT(0);
            }
            __syncthreads();
            compute_stage(st & 1);
            __syncthreads();
        }
    }

    // ---- epilogue: bias + tanh + hi/lo split-store, paired-row layout ----
    const float* sBias = (const float*)(smem + SM_BIAS);
    #pragma unroll
    for (int nt = 0; nt < 8; nt++) {
        int c = wn * 64 + nt * 8 + (l & 3) * 2;
        #pragma unroll
        for (int half = 0; half < 2; half++) {
            int gm = m0 + wm * 16 + (l >> 2) + half * 8;
            float x0 = acc[nt][half * 2]     + sBias[c];
            float x1 = acc[nt][half * 2 + 1] + sBias[c + 1];
            float t0 = tanhf(x0), t1 = tanhf(x1);
            uint32_t hp = f2bf2(t0, t1);
            uint32_t lp = f2bf2(t0 - bf_lo(hp), t1 - bf_hi(hp));
            size_t base = (size_t)(gm >> 1) * 256 + (size_t)((gm & 1) * 128 + c);
            *(uint32_t*)(nHi + base) = hp;
            *(uint32_t*)(nLo + base) = lp;
        }
    }
}

// ---------------- tail kernel: levels Mout=128 down to 1, single CTA, fp32 ----------------
#define SMEM_TAIL (131072 + 65536)
__global__ void __launch_bounds__(512, 1)
rnn_tail(const __nv_bfloat16* __restrict__ Ahi, const __nv_bfloat16* __restrict__ Alo,
         const float* __restrict__ W_l, const float* __restrict__ W_r,
         const float* __restrict__ bsum, float* __restrict__ out) {
    extern __shared__ float fs[];
    float* bufA = fs;                 // 128 x 256 fp32 (128 KB)
    float* bufB = fs + 32768;         // up to 64 x 256 fp32 (64 KB)
    const int tid = threadIdx.x;

    for (int i = tid; i < 128 * 256; i += 512)
        bufA[i] = __bfloat162float(Ahi[i]) + __bfloat162float(Alo[i]);
    __syncthreads();

    float* cur = bufA;
    float* nxt = bufB;
    for (int Mout = 128; Mout >= 1; Mout >>= 1) {
        for (int idx = tid; idx < Mout * 128; idx += 512) {
            int r = idx >> 7, c = idx & 127;
            const float* a = cur + r * 256;
            float s = bsum[c];
            #pragma unroll 8
            for (int k = 0; k < 128; k++) s = fmaf(a[k], W_l[k * 128 + c], s);
            #pragma unroll 8
            for (int k = 0; k < 128; k++) s = fmaf(a[128 + k], W_r[k * 128 + c], s);
            float t = tanhf(s);
            if (Mout == 1) out[c] = t;
            else nxt[(r >> 1) * 256 + (r & 1) * 128 + c] = t;
        }
        __syncthreads();
        float* tmp = cur; cur = nxt; nxt = tmp;
    }
}

// ---------------- host ----------------
extern "C" void kernel_launch(void* const* d_in, const int* in_sizes, int n_in,
                              void* d_out, int out_size) {
    const float* leaf_x = (const float*)d_in[0];
    const float* W_in   = (const float*)d_in[1];
    const float* b_in   = (const float*)d_in[2];
    const float* W_l    = (const float*)d_in[3];
    const float* b_l    = (const float*)d_in[4];
    const float* W_r    = (const float*)d_in[5];
    const float* b_r    = (const float*)d_in[6];

    void *pAh, *pAl, *pBh, *pBl, *pWLh, *pWLl, *pWIh, *pWIl, *pbs;
    cudaGetSymbolAddress(&pAh, g_Ahi);    cudaGetSymbolAddress(&pAl, g_Alo);
    cudaGetSymbolAddress(&pBh, g_Bhi);    cudaGetSymbolAddress(&pBl, g_Blo);
    cudaGetSymbolAddress(&pWLh, g_WLhi);  cudaGetSymbolAddress(&pWLl, g_WLlo);
    cudaGetSymbolAddress(&pWIh, g_WIhi);  cudaGetSymbolAddress(&pWIl, g_WIlo);
    cudaGetSymbolAddress(&pbs, g_bsum);
    __nv_bfloat16 *Ah = (__nv_bfloat16*)pAh, *Al = (__nv_bfloat16*)pAl;
    __nv_bfloat16 *Bh = (__nv_bfloat16*)pBh, *Bl = (__nv_bfloat16*)pBl;
    __nv_bfloat16 *WLh = (__nv_bfloat16*)pWLh, *WLl = (__nv_bfloat16*)pWLl;
    __nv_bfloat16 *WIh = (__nv_bfloat16*)pWIh, *WIl = (__nv_bfloat16*)pWIl;
    float* bsum = (float*)pbs;

    cudaFuncSetAttribute(rnn_level<64, true>,   cudaFuncAttributeMaxDynamicSharedMemorySize, SMEM_LEAF);
    cudaFuncSetAttribute(rnn_level<256, false>, cudaFuncAttributeMaxDynamicSharedMemorySize, SMEM_MAIN);
    cudaFuncSetAttribute(rnn_tail, cudaFuncAttributeMaxDynamicSharedMemorySize, SMEM_TAIL);

    prep_kernel<<<64, 256>>>(W_in, W_l, b_l, W_r, b_r);

    // Leaf: H0[262144,128] -> pairs into (Ah, Al).
    rnn_level<64, true><<<NLV / 128, 512, SMEM_LEAF>>>(
        leaf_x, nullptr, nullptr, WIh, WIl, b_in, Ah, Al);

    // Internal levels while Mout >= 256 (10 launches), ping-pong pairs.
    __nv_bfloat16 *curH = Ah, *curL = Al;
    for (int M = NLV / 2; M >= 256; M >>= 1) {
        __nv_bfloat16* nxtH = (curH == Ah) ? Bh : Ah;
        __nv_bfloat16* nxtL = (curL == Al) ? Bl : Al;
        rnn_level<256, false><<<M / 128, 512, SMEM_MAIN>>>(
            nullptr, curH, curL, WLh, WLl, bsum, nxtH, nxtL);
        curH = nxtH; curL = nxtL;
    }

    // Tail: levels Mout=128..1 in one CTA, fp32, writes d_out[128].
    rnn_tail<<<1, 512, SMEM_TAIL>>>(curH, curL, W_l, W_r, bsum, (float*)d_out);
}